// round 2
// baseline (speedup 1.0000x reference)
#include <cuda_runtime.h>
#include <cuda_bf16.h>

// EWRLS level filter, algebraically reduced:
//   lam = clip(sigmoid(logit_lambda[c]), 1e-4, 1-1e-4)
//   S_t = lam*S_{t-1} + x_t   (S_{-1}=0)
//   Q_t = lam*Q_{t-1} + 1     (Q_{-1}=0)   [data-independent, closed form]
//   y_t = S_t / Q_t
//
// Parallelized over T via 8 chunks of 128 with exact carry fixup
// (decoupled lookback: only S needs a carry; Q is closed-form).

#define B_DIM 64
#define T_DIM 1024
#define C_DIM 512
#define KCH   8            // chunks along T
#define LCH   128          // chunk length (T_DIM / KCH)
#define CT    128          // channels per block == threads per block
#define NTILE (B_DIM * (C_DIM / CT))   // 256 (b, c-tile) pairs
#define NBLK  (NTILE * KCH)            // 2048 blocks

__device__ unsigned int g_ticket;
__device__ unsigned int g_flag[NBLK];
__device__ float        g_carry[NBLK * CT];

__global__ void ewrls_init_kernel() {
    int i = blockIdx.x * blockDim.x + threadIdx.x;
    if (i < NBLK) g_flag[i] = 0u;
    if (i == 0)   g_ticket = 0u;
}

__global__ __launch_bounds__(CT, 3)
void ewrls_chunk_kernel(const float* __restrict__ x,
                        const float* __restrict__ logit_lambda,
                        float* __restrict__ y) {
    extern __shared__ float sx[];          // [LCH][CT] = 64 KB
    __shared__ unsigned s_vid;

    const int tid = threadIdx.x;
    if (tid == 0) s_vid = atomicAdd(&g_ticket, 1u);   // ticket => ordered vids (no deadlock)
    __syncthreads();
    const unsigned vid = s_vid;

    const int chunk = vid / NTILE;         // slow index: chunk 0 blocks get lowest vids
    const int tile  = vid % NTILE;
    const int b     = tile >> 2;           // tile / (C_DIM/CT = 4)
    const int ct    = tile & 3;
    const int c     = ct * CT + tid;
    const int t0    = chunk * LCH;

    // lambda per channel
    float l   = logit_lambda[c];
    float lam = 1.0f / (1.0f + __expf(-l));
    lam = fminf(fmaxf(lam, 1e-4f), 1.0f - 1e-4f);

    // lam^LCH via 7 squarings; lam^t0 = (lam^LCH)^chunk
    float lamL = lam;
#pragma unroll
    for (int i = 0; i < 7; i++) lamL *= lamL;      // lam^128
    float lamT0 = 1.0f;
    {
        float p = lamL; int e = chunk;
        while (e) { if (e & 1) lamT0 *= p; p *= p; e >>= 1; }
    }
    const float Qin = (1.0f - lamT0) / (1.0f - lam);   // Q_{t0-1}, exact closed form

    const float* __restrict__ xp = x + ((size_t)b * T_DIM + t0) * C_DIM + c;
    float*       __restrict__ yp = y + ((size_t)b * T_DIM + t0) * C_DIM + c;

    // ---- sweep 1: load chunk (DRAM), stash into smem, compute local scan ----
    float S = 0.0f;
#pragma unroll 1
    for (int g = 0; g < LCH / 16; g++) {
        float xv[16];
#pragma unroll
        for (int u = 0; u < 16; u++)
            xv[u] = xp[(size_t)(g * 16 + u) * C_DIM];   // 16 independent lines in flight
#pragma unroll
        for (int u = 0; u < 16; u++) {
            sx[(g * 16 + u) * CT + tid] = xv[u];
            S = fmaf(lam, S, xv[u]);                    // local scan from 0
        }
    }

    // ---- carry resolution (decoupled lookback, S only) ----
    float Sin = 0.0f;
    if (chunk > 0) {
        const unsigned pvid = vid - NTILE;
        unsigned f;
        do {
            asm volatile("ld.acquire.gpu.u32 %0, [%1];"
                         : "=r"(f) : "l"(&g_flag[pvid]) : "memory");
            if (f) break;
            __nanosleep(64);
        } while (true);
        __threadfence();
        Sin = g_carry[(size_t)pvid * CT + tid];
    }
    if (chunk < KCH - 1) {
        g_carry[(size_t)vid * CT + tid] = fmaf(lamL, Sin, S);  // true chunk-end S
        __threadfence();          // make carry visible gpu-wide
        __syncthreads();          // all 128 carries written+fenced
        if (tid == 0)
            asm volatile("st.release.gpu.u32 [%0], %1;"
                         :: "l"(&g_flag[vid]), "r"(1u) : "memory");
    }

    // ---- sweep 2: exact recurrence from (Sin, Qin), x from smem, write y ----
    S = Sin;
    float Q = Qin;
#pragma unroll 1
    for (int g = 0; g < LCH / 16; g++) {
        float xv[16];
#pragma unroll
        for (int u = 0; u < 16; u++)
            xv[u] = sx[(g * 16 + u) * CT + tid];
#pragma unroll
        for (int u = 0; u < 16; u++) {
            S = fmaf(lam, S, xv[u]);
            Q = fmaf(lam, Q, 1.0f);
            yp[(size_t)(g * 16 + u) * C_DIM] = __fdividef(S, Q);  // RCP off critical path
        }
    }
}

extern "C" void kernel_launch(void* const* d_in, const int* in_sizes, int n_in,
                              void* d_out, int out_size) {
    const float* x;
    const float* logit_lambda;
    if (in_sizes[0] > in_sizes[1]) {
        x = (const float*)d_in[0];
        logit_lambda = (const float*)d_in[1];
    } else {
        x = (const float*)d_in[1];
        logit_lambda = (const float*)d_in[0];
    }
    float* y = (float*)d_out;

    static_assert(LCH * KCH == T_DIM, "chunking must cover T");

    cudaFuncSetAttribute(ewrls_chunk_kernel,
                         cudaFuncAttributeMaxDynamicSharedMemorySize,
                         LCH * CT * (int)sizeof(float));   // 65536

    // reset ticket + flags every call (graph replays must be deterministic)
    ewrls_init_kernel<<<(NBLK + 255) / 256, 256>>>();
    ewrls_chunk_kernel<<<NBLK, CT, LCH * CT * sizeof(float)>>>(x, logit_lambda, y);
}

// round 3
// speedup vs baseline: 1.1044x; 1.1044x over previous
#include <cuda_runtime.h>
#include <cuda_bf16.h>

// EWRLS level filter, algebraically reduced:
//   lam = clip(sigmoid(logit_lambda[c]), 1e-4, 1-1e-4)
//   S_t = lam*S_{t-1} + x_t   (S_{-1}=0)
//   Q_t = lam*Q_{t-1} + 1     (Q_{-1}=0)
//   y_t = S_t / Q_t
//
// One thread per (b,c) chain. Deep software pipeline: 4-slot circular
// register buffer, prefetch distance 3 -> 24 LDGs in flight per thread.

#define B_DIM 64
#define T_DIM 1024
#define C_DIM 512

#define G     8                 // elements per prefetch group
#define NG    (T_DIM / G)       // 128 groups
#define PD    3                 // prefetch distance (groups in flight)

__device__ __forceinline__ float ldcs(const float* p) {
    float v;
    asm volatile("ld.global.cs.f32 %0, [%1];" : "=f"(v) : "l"(p));
    return v;
}
__device__ __forceinline__ void stcs(float* p, float v) {
    asm volatile("st.global.cs.f32 [%0], %1;" :: "l"(p), "f"(v));
}

__global__ __launch_bounds__(32)
void ewrls_scan_kernel(const float* __restrict__ x,
                       const float* __restrict__ logit_lambda,
                       float* __restrict__ y) {
    const int gtid = blockIdx.x * 32 + threadIdx.x;   // [0, B*C)
    const int c = gtid & (C_DIM - 1);
    const int b = gtid >> 9;

    const size_t base = (size_t)b * T_DIM * C_DIM + c;
    const float* __restrict__ xp = x + base;
    float* __restrict__ yp = y + base;

    float l = __ldg(&logit_lambda[c]);
    float lam = 1.0f / (1.0f + __expf(-l));
    lam = fminf(fmaxf(lam, 1e-4f), 1.0f - 1e-4f);

    float S = 0.0f;
    float Q = 0.0f;

    float buf[PD + 1][G];   // 32 regs

    // prologue: issue groups 0..PD-1
#pragma unroll
    for (int p = 0; p < PD; p++)
#pragma unroll
        for (int u = 0; u < G; u++)
            buf[p][u] = ldcs(xp + (size_t)(p * G + u) * C_DIM);

    // main loop: unrolled by 4 so buffer indices are compile-time
#pragma unroll 1
    for (int i = 0; i < NG; i += 4) {
#pragma unroll
        for (int j = 0; j < 4; j++) {
            const int g = i + j;
            // issue group g+PD into slot (g+PD)&3  (predicated off at the tail)
            if (g + PD < NG) {
                const float* __restrict__ xq = xp + (size_t)((g + PD) * G) * C_DIM;
#pragma unroll
                for (int u = 0; u < G; u++)
                    buf[(j + PD) & 3][u] = ldcs(xq + (size_t)u * C_DIM);
            }
            // consume group g from slot g&3 (issued 3 iterations ago)
            float* __restrict__ yo = yp + (size_t)(g * G) * C_DIM;
#pragma unroll
            for (int u = 0; u < G; u++) {
                S = fmaf(lam, S, buf[j & 3][u]);
                Q = fmaf(lam, Q, 1.0f);
                stcs(yo + (size_t)u * C_DIM, __fdividef(S, Q));
            }
        }
    }
}

extern "C" void kernel_launch(void* const* d_in, const int* in_sizes, int n_in,
                              void* d_out, int out_size) {
    const float* x;
    const float* logit_lambda;
    if (in_sizes[0] > in_sizes[1]) {
        x = (const float*)d_in[0];
        logit_lambda = (const float*)d_in[1];
    } else {
        x = (const float*)d_in[1];
        logit_lambda = (const float*)d_in[0];
    }
    float* y = (float*)d_out;

    const int total = B_DIM * C_DIM;   // 32768 chains
    ewrls_scan_kernel<<<total / 32, 32>>>(x, logit_lambda, y);
}

// round 4
// speedup vs baseline: 1.4647x; 1.3262x over previous
#include <cuda_runtime.h>
#include <cuda_bf16.h>
#include <cstdint>

// EWRLS level filter, algebraically reduced:
//   lam = clip(sigmoid(logit_lambda[c]), 1e-4, 1-1e-4)
//   S_t = lam*S_{t-1} + x_t   (S_{-1}=0)
//   Q_t = lam*Q_{t-1} + 1     (Q_{-1}=0)
//   y_t = S_t / Q_t
//
// cp.async (LDGSTS) 4-stage smem pipeline: loads carry no register scoreboard,
// so in-flight bytes are bounded by smem stages, not register pressure.

#define B_DIM 64
#define T_DIM 1024
#define C_DIM 512

#define CT      128            // channels per block == threads per block
#define TT      32             // timesteps per stage
#define NSTAGE  4
#define NSTG_T  (T_DIM / TT)   // 32 stages per block
#define SMEM_BYTES (NSTAGE * TT * CT * 4)   // 64 KB

__device__ __forceinline__ void cp_async16(uint32_t dst_smem, const void* src) {
    asm volatile("cp.async.cg.shared.global [%0], [%1], 16;"
                 :: "r"(dst_smem), "l"(src));
}
__device__ __forceinline__ void cp_commit() {
    asm volatile("cp.async.commit_group;");
}
template <int N>
__device__ __forceinline__ void cp_wait() {
    asm volatile("cp.async.wait_group %0;" :: "n"(N));
}
__device__ __forceinline__ void stcs(float* p, float v) {
    asm volatile("st.global.cs.f32 [%0], %1;" :: "l"(p), "f"(v));
}

__global__ __launch_bounds__(CT, 2)
void ewrls_scan_kernel(const float* __restrict__ x,
                       const float* __restrict__ logit_lambda,
                       float* __restrict__ y) {
    extern __shared__ float sx[];   // [NSTAGE][TT][CT]

    const int tid   = threadIdx.x;
    const int b     = blockIdx.x >> 2;          // blockIdx / 4
    const int ctile = blockIdx.x & 3;
    const int c     = ctile * CT + tid;

    // lambda per channel
    float l   = __ldg(&logit_lambda[c]);
    float lam = 1.0f / (1.0f + __expf(-l));
    lam = fminf(fmaxf(lam, 1e-4f), 1.0f - 1e-4f);

    const float* __restrict__ xbase =
        x + (size_t)b * T_DIM * C_DIM + (size_t)ctile * CT;
    float* __restrict__ ybase =
        y + (size_t)b * T_DIM * C_DIM + (size_t)ctile * CT + tid;

    uint32_t smem_u32;
    asm("{ .reg .u64 t; cvta.to.shared.u64 t, %1; cvt.u32.u64 %0, t; }"
        : "=r"(smem_u32) : "l"(sx));

    // producer mapping: each thread issues 8x 16B copies per stage
    const int prow = tid >> 5;     // 0..3  (row group)
    const int lane = tid & 31;     // 16B segment within a 512B row

    auto issue_stage = [&](int s) {
        const int buf = s & (NSTAGE - 1);
        const float* __restrict__ g0 = xbase + (size_t)(s * TT) * C_DIM + lane * 4;
        const uint32_t d0 = smem_u32 + ((buf * TT) * CT + lane * 4) * 4;
#pragma unroll
        for (int k = 0; k < TT / 4; k++) {
            const int r = prow + k * 4;
            cp_async16(d0 + r * (CT * 4), g0 + (size_t)r * C_DIM);
        }
    };

    // prologue: stages 0..NSTAGE-2 in flight
#pragma unroll
    for (int s = 0; s < NSTAGE - 1; s++) { issue_stage(s); cp_commit(); }

    float S = 0.0f, Q = 0.0f;

#pragma unroll 1
    for (int i = 0; i < NSTG_T; i++) {
        cp_wait<NSTAGE - 2>();   // stage i's data landed (<=2 groups still in flight)
        __syncthreads();         // visibility + everyone done consuming stage i-1

        if (i + NSTAGE - 1 < NSTG_T) issue_stage(i + NSTAGE - 1);
        cp_commit();             // empty commit at tail keeps group accounting simple

        const int buf = i & (NSTAGE - 1);
        const float* __restrict__ sb = sx + buf * (TT * CT) + tid;
        float* __restrict__ yo = ybase + (size_t)(i * TT) * C_DIM;

#pragma unroll
        for (int g = 0; g < TT / 8; g++) {
            float xv[8];
#pragma unroll
            for (int u = 0; u < 8; u++) xv[u] = sb[(g * 8 + u) * CT];
#pragma unroll
            for (int u = 0; u < 8; u++) {
                S = fmaf(lam, S, xv[u]);
                Q = fmaf(lam, Q, 1.0f);
                stcs(yo + (size_t)(g * 8 + u) * C_DIM, __fdividef(S, Q));
            }
        }
    }
}

extern "C" void kernel_launch(void* const* d_in, const int* in_sizes, int n_in,
                              void* d_out, int out_size) {
    const float* x;
    const float* logit_lambda;
    if (in_sizes[0] > in_sizes[1]) {
        x = (const float*)d_in[0];
        logit_lambda = (const float*)d_in[1];
    } else {
        x = (const float*)d_in[1];
        logit_lambda = (const float*)d_in[0];
    }
    float* y = (float*)d_out;

    cudaFuncSetAttribute(ewrls_scan_kernel,
                         cudaFuncAttributeMaxDynamicSharedMemorySize, SMEM_BYTES);

    const int blocks = B_DIM * (C_DIM / CT);   // 256
    ewrls_scan_kernel<<<blocks, CT, SMEM_BYTES>>>(x, logit_lambda, y);
}